// round 4
// baseline (speedup 1.0000x reference)
#include <cuda_runtime.h>
#include <cstdint>

// ---------------- problem dims ----------------
#define T_DIM 8192
#define D_DIM 1024
#define H_DIM 4096

// scratch (device globals: no allocation allowed)
__device__ float g_h  [(size_t)T_DIM * H_DIM];   // 128 MB intermediate
__device__ float g_xr [(size_t)T_DIM * D_DIM];   // tf32-rounded x
__device__ float g_wfc[(size_t)H_DIM * D_DIM];   // tf32-rounded W_fc
__device__ float g_wpr[(size_t)D_DIM * H_DIM];   // tf32-rounded W_proj

// ---------------- helpers ----------------
__device__ __forceinline__ uint32_t smem_u32(const void* p) {
    uint32_t a;
    asm("{ .reg .u64 t; cvta.to.shared.u64 t, %1; cvt.u32.u64 %0, t; }" : "=r"(a) : "l"(p));
    return a;
}
__device__ __forceinline__ uint32_t swz(uint32_t b) {   // SW128: XOR bits[6:4] with bits[9:7]
    return b ^ ((b >> 3) & 0x70u);
}
__device__ __forceinline__ void cp_async16(uint32_t saddr, const void* g) {
    asm volatile("cp.async.cg.shared.global [%0], [%1], 16;" :: "r"(saddr), "l"(g));
}
#define CP_COMMIT() asm volatile("cp.async.commit_group;" ::: "memory")
#define CP_WAIT2()  asm volatile("cp.async.wait_group 2;" ::: "memory")

#define LDSM_X4(r0, r1, r2, r3, addr) \
    asm volatile("ldmatrix.sync.aligned.m8n8.x4.shared.b16 {%0,%1,%2,%3}, [%4];" \
        : "=r"(r0), "=r"(r1), "=r"(r2), "=r"(r3) : "r"(addr))

#define MMA_TF32(c0, c1, c2, c3, a0, a1, a2, a3, b0, b1) \
    asm volatile("mma.sync.aligned.m16n8k8.row.col.f32.tf32.tf32.f32 " \
        "{%0,%1,%2,%3}, {%4,%5,%6,%7}, {%8,%9}, {%0,%1,%2,%3};" \
        : "+f"(c0), "+f"(c1), "+f"(c2), "+f"(c3) \
        : "r"(a0), "r"(a1), "r"(a2), "r"(a3), "r"(b0), "r"(b1))

// ---------------- GEMM config ----------------
static constexpr int BLK_M = 256;
static constexpr int BLK_N = 128;
static constexpr int BLK_K = 32;                 // 128 bytes per row
static constexpr int STAGES = 4;
static constexpr int A_BYTES = BLK_M * BLK_K * 4;          // 32768
static constexpr int B_BYTES = BLK_N * BLK_K * 4;          // 16384
static constexpr int STAGE_BYTES = A_BYTES + B_BYTES;      // 49152
static constexpr int SMEM_TOTAL = STAGES * STAGE_BYTES;    // 196608

// load one 256x32 A tile + 128x32 B tile into stage at sBase (256 threads)
__device__ __forceinline__ void load_tile(uint32_t sBase, const float* __restrict__ gA,
                                          const float* __restrict__ gB, int K, int kt, int tid)
{
    const int k0 = kt * BLK_K;
    #pragma unroll
    for (int i = 0; i < 8; ++i) {                  // A: 2048 x 16B chunks / 256 thr
        int chunk = tid + i * 256;
        int row = chunk >> 3, unit = chunk & 7;
        uint32_t off = row * 128 + unit * 16;
        cp_async16(sBase + swz(off), gA + (size_t)row * K + k0 + unit * 4);
    }
    #pragma unroll
    for (int i = 0; i < 4; ++i) {                  // B: 1024 chunks
        int chunk = tid + i * 256;
        int row = chunk >> 3, unit = chunk & 7;
        uint32_t off = row * 128 + unit * 16;
        cp_async16(sBase + A_BYTES + swz(off), gB + (size_t)row * K + k0 + unit * 4);
    }
}

template <bool RELU2>
__global__ void __launch_bounds__(256, 1) gemm_tf32_mma(
    const float* __restrict__ A,   // [M, K] row-major (K contiguous)
    const float* __restrict__ B,   // [N, K] row-major (K contiguous)
    float* __restrict__ C,         // [M, N]
    int K, int ldc)
{
    extern __shared__ char smem[];
    const uint32_t sb = smem_u32(smem);
    const int tid  = threadIdx.x;
    const int lane = tid & 31;
    const int warp = tid >> 5;
    const int wm = (warp & 3) * 64;        // warp grid 4x2, warp tile 64x64
    const int wn = (warp >> 2) * 64;

    const float* gA = A + (size_t)blockIdx.x * BLK_M * K;
    const float* gB = B + (size_t)blockIdx.y * BLK_N * K;
    const int KT = K / BLK_K;

    // prologue: 3 stages in flight
    #pragma unroll
    for (int p = 0; p < 3; ++p) {
        load_tile(sb + p * STAGE_BYTES, gA, gB, K, p, tid);
        CP_COMMIT();
    }

    // ldmatrix linear offsets (swizzle XOR applied per access)
    const uint32_t xmask = (uint32_t)(lane & 7) << 4;
    uint32_t aLin[4], bLin[4];
    #pragma unroll
    for (int mi = 0; mi < 4; ++mi)
        aLin[mi] = (uint32_t)(wm + mi * 16 + (lane & 15)) * 128 + (uint32_t)(lane >> 4) * 16;
    #pragma unroll
    for (int jp = 0; jp < 4; ++jp)
        bLin[jp] = (uint32_t)(wn + jp * 16 + (lane & 15)) * 128 + (uint32_t)(lane >> 4) * 16;

    float c[4][8][4];
    #pragma unroll
    for (int mi = 0; mi < 4; ++mi)
        #pragma unroll
        for (int j = 0; j < 8; ++j)
            #pragma unroll
            for (int q = 0; q < 4; ++q) c[mi][j][q] = 0.0f;

    uint32_t fa[2][4][4], fb[2][4][4];   // double-buffered fragments

    int curSt = 0, pfSt = 3;
    for (int kt = 0; kt < KT; ++kt) {
        CP_WAIT2();
        __syncthreads();

        // prefetch k-tile kt+3 into the stage consumed at kt-1
        int nk = kt + 3;
        if (nk < KT) load_tile(sb + pfSt * STAGE_BYTES, gA, gB, K, nk, tid);
        CP_COMMIT();
        pfSt = (pfSt + 1) & 3;

        const uint32_t st = sb + curSt * STAGE_BYTES;
        curSt = (curSt + 1) & 3;

        // load fragments for step 0
        #pragma unroll
        for (int mi = 0; mi < 4; ++mi)
            LDSM_X4(fa[0][mi][0], fa[0][mi][1], fa[0][mi][2], fa[0][mi][3],
                    st + (aLin[mi] ^ xmask));
        #pragma unroll
        for (int jp = 0; jp < 4; ++jp)
            LDSM_X4(fb[0][jp][0], fb[0][jp][1], fb[0][jp][2], fb[0][jp][3],
                    st + A_BYTES + (bLin[jp] ^ xmask));

        #pragma unroll
        for (int s = 0; s < 4; ++s) {              // 4 x K=8 steps
            const int cur = s & 1, nxt = cur ^ 1;
            if (s < 3) {                            // prefetch next step's fragments
                const uint32_t add = (s + 1) * 32;
                #pragma unroll
                for (int mi = 0; mi < 4; ++mi)
                    LDSM_X4(fa[nxt][mi][0], fa[nxt][mi][1], fa[nxt][mi][2], fa[nxt][mi][3],
                            st + ((aLin[mi] + add) ^ xmask));
                #pragma unroll
                for (int jp = 0; jp < 4; ++jp)
                    LDSM_X4(fb[nxt][jp][0], fb[nxt][jp][1], fb[nxt][jp][2], fb[nxt][jp][3],
                            st + A_BYTES + ((bLin[jp] + add) ^ xmask));
            }
            #pragma unroll
            for (int mi = 0; mi < 4; ++mi)
                #pragma unroll
                for (int jp = 0; jp < 4; ++jp) {
                    MMA_TF32(c[mi][2 * jp][0], c[mi][2 * jp][1], c[mi][2 * jp][2], c[mi][2 * jp][3],
                             fa[cur][mi][0], fa[cur][mi][1], fa[cur][mi][2], fa[cur][mi][3],
                             fb[cur][jp][0], fb[cur][jp][2]);
                    MMA_TF32(c[mi][2 * jp + 1][0], c[mi][2 * jp + 1][1], c[mi][2 * jp + 1][2], c[mi][2 * jp + 1][3],
                             fa[cur][mi][0], fa[cur][mi][1], fa[cur][mi][2], fa[cur][mi][3],
                             fb[cur][jp][1], fb[cur][jp][3]);
                }
        }
    }

    // epilogue: direct STG.64, fragment layout d0..d3
    const int row0 = blockIdx.x * BLK_M + wm + (lane >> 2);
    const int col0 = blockIdx.y * BLK_N + wn + (lane & 3) * 2;
    #pragma unroll
    for (int mi = 0; mi < 4; ++mi)
        #pragma unroll
        for (int rr = 0; rr < 2; ++rr) {
            const int row = row0 + mi * 16 + rr * 8;
            float* base = C + (size_t)row * ldc + col0;
            #pragma unroll
            for (int j = 0; j < 8; ++j) {
                float v0 = c[mi][j][rr * 2], v1 = c[mi][j][rr * 2 + 1];
                if (RELU2) {
                    v0 = fmaxf(v0, 0.0f); v0 *= v0;
                    v1 = fmaxf(v1, 0.0f); v1 *= v1;
                    uint32_t u0, u1;
                    asm("cvt.rna.tf32.f32 %0, %1;" : "=r"(u0) : "f"(v0));
                    asm("cvt.rna.tf32.f32 %0, %1;" : "=r"(u1) : "f"(v1));
                    v0 = __uint_as_float(u0); v1 = __uint_as_float(u1);
                }
                *reinterpret_cast<float2*>(base + j * 8) = make_float2(v0, v1);
            }
        }
}

// ---------------- tf32 round-to-nearest pre-pass ----------------
__global__ void round_tf32_kernel(const float4* __restrict__ in, uint4* __restrict__ out, int n4)
{
    int i = blockIdx.x * blockDim.x + threadIdx.x;
    if (i >= n4) return;
    float4 v = in[i];
    uint4 o;
    asm("cvt.rna.tf32.f32 %0, %1;" : "=r"(o.x) : "f"(v.x));
    asm("cvt.rna.tf32.f32 %0, %1;" : "=r"(o.y) : "f"(v.y));
    asm("cvt.rna.tf32.f32 %0, %1;" : "=r"(o.z) : "f"(v.z));
    asm("cvt.rna.tf32.f32 %0, %1;" : "=r"(o.w) : "f"(v.w));
    out[i] = o;
}

// ---------------- host side ----------------
extern "C" void kernel_launch(void* const* d_in, const int* in_sizes, int n_in,
                              void* d_out, int out_size)
{
    const float* x   = (const float*)d_in[0];  // [8192, 1024]
    const float* wfc = (const float*)d_in[1];  // [4096, 1024]
    const float* wpr = (const float*)d_in[2];  // [1024, 4096]
    float* out = (float*)d_out;                // [8192, 1024]

    float *h, *xr, *wfcr, *wprr;
    cudaGetSymbolAddress((void**)&h,    g_h);
    cudaGetSymbolAddress((void**)&xr,   g_xr);
    cudaGetSymbolAddress((void**)&wfcr, g_wfc);
    cudaGetSymbolAddress((void**)&wprr, g_wpr);

    cudaFuncSetAttribute(gemm_tf32_mma<true>,
                         cudaFuncAttributeMaxDynamicSharedMemorySize, SMEM_TOTAL);
    cudaFuncSetAttribute(gemm_tf32_mma<false>,
                         cudaFuncAttributeMaxDynamicSharedMemorySize, SMEM_TOTAL);

    // tf32 RN pre-rounding (truncation bias would exceed the 1e-3 budget)
    {
        int n4x = T_DIM * D_DIM / 4;
        int n4f = H_DIM * D_DIM / 4;
        int n4p = D_DIM * H_DIM / 4;
        round_tf32_kernel<<<(n4x + 255) / 256, 256>>>((const float4*)x,   (uint4*)xr,   n4x);
        round_tf32_kernel<<<(n4f + 255) / 256, 256>>>((const float4*)wfc, (uint4*)wfcr, n4f);
        round_tf32_kernel<<<(n4p + 255) / 256, 256>>>((const float4*)wpr, (uint4*)wprr, n4p);
    }

    // GEMM1: h = relu(x @ Wfc^T)^2   [8192, 4096], K = 1024
    gemm_tf32_mma<true><<<dim3(T_DIM / BLK_M, H_DIM / BLK_N), 256, SMEM_TOTAL>>>(
        xr, wfcr, h, D_DIM, H_DIM);

    // GEMM2: out = h @ Wpr^T         [8192, 1024], K = 4096
    gemm_tf32_mma<false><<<dim3(T_DIM / BLK_M, D_DIM / BLK_N), 256, SMEM_TOTAL>>>(
        h, wprr, out, H_DIM, D_DIM);
}

// round 5
// speedup vs baseline: 2.0549x; 2.0549x over previous
#include <cuda_runtime.h>
#include <cuda_fp16.h>
#include <cstdint>

// ---------------- problem dims ----------------
#define T_DIM 8192
#define D_DIM 1024
#define H_DIM 4096

// scratch (device globals: no allocation allowed)
__device__ __half g_h  [(size_t)T_DIM * H_DIM];   // 64 MB intermediate (fp16)
__device__ __half g_xh [(size_t)T_DIM * D_DIM];   // fp16 x
__device__ __half g_wfc[(size_t)H_DIM * D_DIM];   // fp16 W_fc
__device__ __half g_wpr[(size_t)D_DIM * H_DIM];   // fp16 W_proj

// ---------------- helpers ----------------
__device__ __forceinline__ uint32_t smem_u32(const void* p) {
    uint32_t a;
    asm("{ .reg .u64 t; cvta.to.shared.u64 t, %1; cvt.u32.u64 %0, t; }" : "=r"(a) : "l"(p));
    return a;
}
__device__ __forceinline__ uint32_t swz(uint32_t b) {   // SW128: XOR bits[6:4] with bits[9:7]
    return b ^ ((b >> 3) & 0x70u);
}
__device__ __forceinline__ void cp_async16(uint32_t saddr, const void* g) {
    asm volatile("cp.async.cg.shared.global [%0], [%1], 16;" :: "r"(saddr), "l"(g));
}
#define CP_COMMIT() asm volatile("cp.async.commit_group;" ::: "memory")
#define CP_WAIT1()  asm volatile("cp.async.wait_group 1;" ::: "memory")

#define LDSM_X4(r0, r1, r2, r3, addr) \
    asm volatile("ldmatrix.sync.aligned.m8n8.x4.shared.b16 {%0,%1,%2,%3}, [%4];" \
        : "=r"(r0), "=r"(r1), "=r"(r2), "=r"(r3) : "r"(addr))

// fp16 MMA, fp32 accumulate: D(16x8) += A(16x16) * B(16x8)
#define MMA_F16(c0, c1, c2, c3, a0, a1, a2, a3, b0, b1) \
    asm volatile("mma.sync.aligned.m16n8k16.row.col.f32.f16.f16.f32 " \
        "{%0,%1,%2,%3}, {%4,%5,%6,%7}, {%8,%9}, {%0,%1,%2,%3};" \
        : "+f"(c0), "+f"(c1), "+f"(c2), "+f"(c3) \
        : "r"(a0), "r"(a1), "r"(a2), "r"(a3), "r"(b0), "r"(b1))

// ---------------- GEMM config ----------------
static constexpr int BLK_M = 128;
static constexpr int BLK_N = 128;
static constexpr int BLK_K = 64;                 // fp16 elems -> 128 bytes per row
static constexpr int STAGES = 3;                 // 96KB -> 2 CTAs / SM
static constexpr int A_BYTES = BLK_M * BLK_K * 2;          // 16384
static constexpr int B_BYTES = BLK_N * BLK_K * 2;          // 16384
static constexpr int STAGE_BYTES = A_BYTES + B_BYTES;      // 32768
static constexpr int SMEM_TOTAL = STAGES * STAGE_BYTES;    // 98304

// load one 128x64 A tile + 128x64 B tile (fp16) into stage at sBase
__device__ __forceinline__ void load_tile(uint32_t sBase, const __half* __restrict__ gA,
                                          const __half* __restrict__ gB, int K, int kt, int tid)
{
    const int k0 = kt * BLK_K;
    #pragma unroll
    for (int i = 0; i < 4; ++i) {                  // A: 1024 x 16B chunks / 256 thr
        int chunk = tid + i * 256;
        int row = chunk >> 3, unit = chunk & 7;    // 8 x 16B units per 128B row
        uint32_t off = row * 128 + unit * 16;
        cp_async16(sBase + swz(off), gA + (size_t)row * K + k0 + unit * 8);
    }
    #pragma unroll
    for (int i = 0; i < 4; ++i) {                  // B
        int chunk = tid + i * 256;
        int row = chunk >> 3, unit = chunk & 7;
        uint32_t off = row * 128 + unit * 16;
        cp_async16(sBase + A_BYTES + swz(off), gB + (size_t)row * K + k0 + unit * 8);
    }
}

// OUT16: write C as fp16 (GEMM1 -> h). Otherwise fp32.
template <bool RELU2, bool OUT16>
__global__ void __launch_bounds__(256, 2) gemm_f16_mma(
    const __half* __restrict__ A,   // [M, K] row-major (K contiguous)
    const __half* __restrict__ B,   // [N, K] row-major (K contiguous)
    void* __restrict__ Cv,          // [M, N]
    int K, int ldc)
{
    extern __shared__ char smem[];
    const uint32_t sb = smem_u32(smem);
    const int tid  = threadIdx.x;
    const int lane = tid & 31;
    const int warp = tid >> 5;
    const int wm = (warp & 3) * 32;        // warp grid 4x2, warp tile 32x64
    const int wn = (warp >> 2) * 64;

    const __half* gA = A + (size_t)blockIdx.x * BLK_M * K;
    const __half* gB = B + (size_t)blockIdx.y * BLK_N * K;
    const int KT = K / BLK_K;

    // prologue: 2 stages in flight
    load_tile(sb, gA, gB, K, 0, tid);
    CP_COMMIT();
    load_tile(sb + STAGE_BYTES, gA, gB, K, 1, tid);
    CP_COMMIT();

    // ldmatrix linear offsets (swizzle XOR applied per access).
    // 128B rows; lanes 0-15 -> rows, lanes 16-31 -> +16B (k8..15 halves)
    const uint32_t xmask = (uint32_t)(lane & 7) << 4;
    const uint32_t aLin0 = (uint32_t)(wm + (lane & 15)) * 128 + (uint32_t)(lane >> 4) * 16;
    const uint32_t aLin1 = aLin0 + 16 * 128;
    uint32_t bLin[4];
    #pragma unroll
    for (int jp = 0; jp < 4; ++jp)
        bLin[jp] = (uint32_t)(wn + jp * 16 + (lane & 15)) * 128 + (uint32_t)(lane >> 4) * 16;

    float c[2][8][4];
    #pragma unroll
    for (int mi = 0; mi < 2; ++mi)
        #pragma unroll
        for (int j = 0; j < 8; ++j)
            #pragma unroll
            for (int q = 0; q < 4; ++q) c[mi][j][q] = 0.0f;

    int curSt = 0, pfSt = 2;
    for (int kt = 0; kt < KT; ++kt) {
        CP_WAIT1();
        __syncthreads();

        // prefetch k-tile kt+2 into the slot consumed at kt-1
        int nk = kt + 2;
        if (nk < KT) load_tile(sb + pfSt * STAGE_BYTES, gA, gB, K, nk, tid);
        CP_COMMIT();
        if (++pfSt == STAGES) pfSt = 0;

        const uint32_t st = sb + curSt * STAGE_BYTES;
        if (++curSt == STAGES) curSt = 0;

        #pragma unroll
        for (int s = 0; s < 4; ++s) {              // 4 x K=16 steps (32B each)
            const uint32_t add = s * 32;
            uint32_t a[2][4], b[4][4];
            // A: 16x16 fp16 per x4 (m0=r0-7 k0-7, m1=r8-15 k0-7, m2=r0-7 k8-15, m3=r8-15 k8-15)
            LDSM_X4(a[0][0], a[0][1], a[0][2], a[0][3], st + ((aLin0 + add) ^ xmask));
            LDSM_X4(a[1][0], a[1][1], a[1][2], a[1][3], st + ((aLin1 + add) ^ xmask));
            // B: 16n x 16k per x4 -> regs (n0-7 b0, n8-15 b0, n0-7 b1, n8-15 b1)
            #pragma unroll
            for (int jp = 0; jp < 4; ++jp)
                LDSM_X4(b[jp][0], b[jp][1], b[jp][2], b[jp][3],
                        st + A_BYTES + ((bLin[jp] + add) ^ xmask));
            #pragma unroll
            for (int mi = 0; mi < 2; ++mi)
                #pragma unroll
                for (int jp = 0; jp < 4; ++jp) {
                    MMA_F16(c[mi][2 * jp][0], c[mi][2 * jp][1], c[mi][2 * jp][2], c[mi][2 * jp][3],
                            a[mi][0], a[mi][1], a[mi][2], a[mi][3], b[jp][0], b[jp][2]);
                    MMA_F16(c[mi][2 * jp + 1][0], c[mi][2 * jp + 1][1], c[mi][2 * jp + 1][2], c[mi][2 * jp + 1][3],
                            a[mi][0], a[mi][1], a[mi][2], a[mi][3], b[jp][1], b[jp][3]);
                }
        }
    }

    // epilogue
    const int row0 = blockIdx.x * BLK_M + wm + (lane >> 2);
    const int col0 = blockIdx.y * BLK_N + wn + (lane & 3) * 2;
    #pragma unroll
    for (int mi = 0; mi < 2; ++mi)
        #pragma unroll
        for (int rr = 0; rr < 2; ++rr) {
            const int row = row0 + mi * 16 + rr * 8;
            #pragma unroll
            for (int j = 0; j < 8; ++j) {
                float v0 = c[mi][j][rr * 2], v1 = c[mi][j][rr * 2 + 1];
                if (RELU2) {
                    v0 = fmaxf(v0, 0.0f); v0 *= v0;
                    v1 = fmaxf(v1, 0.0f); v1 *= v1;
                }
                if (OUT16) {
                    __half* base = (__half*)Cv + (size_t)row * ldc + col0;
                    __half2 hv = __floats2half2_rn(v0, v1);
                    *reinterpret_cast<__half2*>(base + j * 8) = hv;
                } else {
                    float* base = (float*)Cv + (size_t)row * ldc + col0;
                    *reinterpret_cast<float2*>(base + j * 8) = make_float2(v0, v1);
                }
            }
        }
}

// ---------------- fp32 -> fp16 RN pre-pass ----------------
__global__ void to_half_kernel(const float4* __restrict__ in, __half2* __restrict__ out, int n4)
{
    int i = blockIdx.x * blockDim.x + threadIdx.x;
    if (i >= n4) return;
    float4 v = in[i];
    out[2 * i]     = __floats2half2_rn(v.x, v.y);
    out[2 * i + 1] = __floats2half2_rn(v.z, v.w);
}

// ---------------- host side ----------------
extern "C" void kernel_launch(void* const* d_in, const int* in_sizes, int n_in,
                              void* d_out, int out_size)
{
    const float* x   = (const float*)d_in[0];  // [8192, 1024]
    const float* wfc = (const float*)d_in[1];  // [4096, 1024]
    const float* wpr = (const float*)d_in[2];  // [1024, 4096]
    float* out = (float*)d_out;                // [8192, 1024]

    __half *h, *xh, *wfch, *wprh;
    cudaGetSymbolAddress((void**)&h,    g_h);
    cudaGetSymbolAddress((void**)&xh,   g_xh);
    cudaGetSymbolAddress((void**)&wfch, g_wfc);
    cudaGetSymbolAddress((void**)&wprh, g_wpr);

    cudaFuncSetAttribute(gemm_f16_mma<true, true>,
                         cudaFuncAttributeMaxDynamicSharedMemorySize, SMEM_TOTAL);
    cudaFuncSetAttribute(gemm_f16_mma<false, false>,
                         cudaFuncAttributeMaxDynamicSharedMemorySize, SMEM_TOTAL);

    // fp32 -> fp16 (RN) pre-pass; fp16 mantissa == tf32 mantissa (11 bits effective)
    {
        int n4x = T_DIM * D_DIM / 4;
        int n4f = H_DIM * D_DIM / 4;
        int n4p = D_DIM * H_DIM / 4;
        to_half_kernel<<<(n4x + 255) / 256, 256>>>((const float4*)x,   (__half2*)xh,   n4x);
        to_half_kernel<<<(n4f + 255) / 256, 256>>>((const float4*)wfc, (__half2*)wfch, n4f);
        to_half_kernel<<<(n4p + 255) / 256, 256>>>((const float4*)wpr, (__half2*)wprh, n4p);
    }

    // GEMM1: h = relu(x @ Wfc^T)^2   [8192, 4096], K = 1024, out fp16
    gemm_f16_mma<true, true><<<dim3(T_DIM / BLK_M, H_DIM / BLK_N), 256, SMEM_TOTAL>>>(
        xh, wfch, h, D_DIM, H_DIM);

    // GEMM2: out = h @ Wpr^T         [8192, 1024], K = 4096, out fp32
    gemm_f16_mma<false, false><<<dim3(T_DIM / BLK_M, D_DIM / BLK_N), 256, SMEM_TOTAL>>>(
        h, wprh, out, H_DIM, D_DIM);
}